// round 14
// baseline (speedup 1.0000x reference)
#include <cuda_runtime.h>
#include <cuda_fp16.h>
#include <cstdint>

// Problem constants
#define BATCH 4
#define SEQ   2048
#define DMODEL 1024
#define NHEAD 16
#define DHEAD 64
#define MROWS (BATCH * SEQ)                       // 8192
#define OUT_ELEMS ((size_t)BATCH * SEQ * DMODEL)  // 8388608
#define GK 2048                                   // fp16 2-term K (2 x 1024)
#define SK 128                                    // fp16 2-term K for scores
#define NZ (BATCH * NHEAD)                        // 64 head-slices
#define VK 4096                                   // fp16 2-term K_eff for AV

// ---------------------------------------------------------------------------
// Scratch (device globals; allocation-free rule)
// ---------------------------------------------------------------------------
__device__ __half g_qs [(size_t)MROWS * GK];    // activations [hi | lo]
__device__ __half g_ks [(size_t)MROWS * GK];
__device__ __half g_vs [(size_t)MROWS * GK];
__device__ __half g_ohs[(size_t)MROWS * GK];
__device__ __half g_wqs[(size_t)DMODEL * GK];   // weights^T [hi | hi]
__device__ __half g_wks[(size_t)DMODEL * GK];
__device__ __half g_wvs[(size_t)DMODEL * GK];
__device__ __half g_wos[(size_t)DMODEL * GK];
__device__ __half g_qsp[(size_t)NZ * SEQ * SK]; // Q heads [hi|lo], pre-scaled 0.125
__device__ __half g_ksp[(size_t)NZ * SEQ * SK]; // K heads [hi|hi]
__device__ __half g_vsp[(size_t)NZ * DHEAD * VK]; // V^T, per-32-chunk [hi|hi]
__device__ __half g_eh [(size_t)NZ * SEQ * SEQ]; // unnormalized exp(score), fp16
__device__ float g_psum[(size_t)NZ * SEQ * 16];

// ---------------------------------------------------------------------------
// MMA / async-copy helpers
// ---------------------------------------------------------------------------
__device__ __forceinline__ uint32_t smem_u32(const void* p) {
    uint32_t a;
    asm("{ .reg .u64 t; cvta.to.shared.u64 t, %1; cvt.u32.u64 %0, t; }"
        : "=r"(a) : "l"(p));
    return a;
}

#define LDSM_X4(r0, r1, r2, r3, addr)                                          \
    asm volatile("ldmatrix.sync.aligned.m8n8.x4.shared.b16 {%0,%1,%2,%3}, [%4];" \
                 : "=r"(r0), "=r"(r1), "=r"(r2), "=r"(r3) : "r"(addr))

#define MMA16816(d, a, b)                                                      \
    asm volatile("mma.sync.aligned.m16n8k16.row.col.f32.f16.f16.f32 "          \
                 "{%0,%1,%2,%3}, {%4,%5,%6,%7}, {%8,%9}, {%0,%1,%2,%3};"       \
                 : "+f"((d)[0]), "+f"((d)[1]), "+f"((d)[2]), "+f"((d)[3])      \
                 : "r"((a)[0]), "r"((a)[1]), "r"((a)[2]), "r"((a)[3]),         \
                   "r"((b)[0]), "r"((b)[1]))

#define CP_ASYNC16(dst, src)                                                   \
    asm volatile("cp.async.cg.shared.global [%0], [%1], 16;"                   \
                 :: "r"(dst), "l"(src))
#define CP_COMMIT() asm volatile("cp.async.commit_group;" ::: "memory")
#define CP_WAIT(n)  asm volatile("cp.async.wait_group %0;" :: "n"(n) : "memory")

__device__ __forceinline__ uint32_t pack_h2(__half a, __half b) {
    __half2 h = __halves2half2(a, b);
    return *(uint32_t*)&h;
}

// One pipeline stage: A[128][40] then B[128][40] halves (80 B row stride).
#define TSTAGE 20480u
#define MAIN_SMEM (4 * 20480)     // 81920 (proj: 4-stage, 2 CTAs/SM)
#define SC_SMEM  (3 * 20480)      // 61440 (scores: 3-stage, 3 CTAs/SM)

// Core loop: CTA 128x128, 8 warps (2Mx4N), K-step 32,
// STAGES-deep cp.async pipeline. nIters >= STAGES-1.
template <int STAGES>
__device__ __forceinline__ void mma_loop_128x128(
    char* smem, const __half* __restrict__ Abase,
    const __half* __restrict__ Bbase,
    int lda, int ldb, int nIters, float acc[4][4][4])
{
    const int tid  = threadIdx.x;
    const int lane = tid & 31;
    const int warp = tid >> 5;
    const int wm = (warp >> 2) * 64;
    const int wn = (warp & 3) * 32;

    const int grow = tid >> 2;
    const int gcol = (tid & 3) * 8;
    const __half* Ap = Abase + (size_t)grow * lda + gcol;
    const __half* Bp = Bbase + (size_t)grow * ldb + gcol;

    const uint32_t s0 = smem_u32(smem);
    const uint32_t aStOff = (uint32_t)(grow * 80 + gcol * 2);
    const uint32_t bStOff = 10240u + (uint32_t)(grow * 80 + gcol * 2);

    const int mrow  = lane & 15;
    const int kA    = (lane & 16) ? 16 : 0;
    const int nrow  = (lane & 7) + ((lane & 16) ? 8 : 0);
    const int kB    = (lane & 8) ? 16 : 0;
    const uint32_t aLdm = s0 + (uint32_t)((wm + mrow) * 80 + kA);
    const uint32_t bLdm = s0 + 10240u + (uint32_t)((wn + nrow) * 80 + kB);

#define ISSUE_TILE(g)                                                          \
    do {                                                                       \
        const uint32_t st = s0 + (uint32_t)((g) % STAGES) * TSTAGE;            \
        const __half* An = Ap + (g) * 32;                                      \
        const __half* Bn = Bp + (g) * 32;                                      \
        CP_ASYNC16(st + aStOff, An);                                           \
        CP_ASYNC16(st + aStOff + 64u * 80u, An + (size_t)64 * lda);            \
        CP_ASYNC16(st + bStOff, Bn);                                           \
        CP_ASYNC16(st + bStOff + 64u * 80u, Bn + (size_t)64 * ldb);            \
        CP_COMMIT();                                                           \
    } while (0)

#pragma unroll
    for (int p = 0; p < STAGES - 1; ++p) ISSUE_TILE(p);

    for (int it = 0; it < nIters; ++it) {
        const int rem = nIters - 1 - it;   // tiles after this one
        if (STAGES >= 4 && rem >= 2)      { CP_WAIT(2); }
        else if (rem >= 1)                { CP_WAIT(1); }
        else                              { CP_WAIT(0); }
        __syncthreads();
        if (it + STAGES - 1 < nIters) ISSUE_TILE(it + STAGES - 1);

        const uint32_t cur = (uint32_t)(it % STAGES) * TSTAGE;
#pragma unroll
        for (int ks = 0; ks < 2; ++ks) {
            uint32_t a[4][4], b[4][2];
#pragma unroll
            for (int mi = 0; mi < 4; ++mi)
                LDSM_X4(a[mi][0], a[mi][1], a[mi][2], a[mi][3],
                        aLdm + cur + (uint32_t)(mi * 16 * 80 + ks * 32));
            LDSM_X4(b[0][0], b[0][1], b[1][0], b[1][1],
                    bLdm + cur + (uint32_t)(ks * 32));
            LDSM_X4(b[2][0], b[2][1], b[3][0], b[3][1],
                    bLdm + cur + (uint32_t)(16 * 80 + ks * 32));
#pragma unroll
            for (int mi = 0; mi < 4; ++mi)
#pragma unroll
                for (int ni = 0; ni < 4; ++ni)
                    MMA16816(acc[mi][ni], a[mi], b[ni]);
        }
    }
#undef ISSUE_TILE
}

// ---------------------------------------------------------------------------
// Merged Q/K/V projection: grid (8, 64, 3). z=0:Q, z=1:K, z=2:V.
// ---------------------------------------------------------------------------
struct QKVArgs {
    const __half* A[3];
    const __half* W[3];
    const float*  bias[3];
    __half*       C[3];
};

__global__ __launch_bounds__(256) void proj_qkv(QKVArgs args)
{
    extern __shared__ char smem[];
    const int zk = blockIdx.z;       // 0=Q, 1=K, 2=V
    const int mbase = blockIdx.y * 128;
    const int nbase = blockIdx.x * 128;

    const __half* Ag = args.A[zk];
    const __half* Bg = args.W[zk];
    const float* bias = args.bias[zk];
    __half* Cs = args.C[zk];

    float acc[4][4][4];
#pragma unroll
    for (int i = 0; i < 4; i++)
#pragma unroll
        for (int j = 0; j < 4; j++)
#pragma unroll
            for (int r = 0; r < 4; r++) acc[i][j][r] = 0.0f;

    mma_loop_128x128<4>(smem, Ag + (size_t)mbase * GK, Bg + (size_t)nbase * GK,
                        GK, GK, GK / 32, acc);

    const int lane = threadIdx.x & 31;
    const int warp = threadIdx.x >> 5;
    const int wm = (warp >> 2) * 64;
    const int wn = (warp & 3) * 32;
    const int g = lane >> 2, tg = lane & 3;

#pragma unroll
    for (int mi = 0; mi < 4; ++mi) {
#pragma unroll
        for (int ni = 0; ni < 4; ++ni) {
#pragma unroll
            for (int half = 0; half < 2; ++half) {
                const int m = mbase + wm + mi * 16 + g + half * 8;
                const int n0 = nbase + wn + ni * 8 + tg * 2;
                float v0 = acc[mi][ni][half * 2 + 0] + bias[n0];
                float v1 = acc[mi][ni][half * 2 + 1] + bias[n0 + 1];
                const int z = ((m >> 11) << 4) + (n0 >> 6);
                const int s = m & (SEQ - 1);
                const int d = n0 & 63;
                if (zk == 0) { v0 *= 0.125f; v1 *= 0.125f; }
                const __half h0 = __float2half_rn(v0);
                const __half h1 = __float2half_rn(v1);
                if (zk == 0) {           // Q: [hi | lo], pre-scaled
                    const __half l0 = __float2half_rn(v0 - __half2float(h0));
                    const __half l1 = __float2half_rn(v1 - __half2float(h1));
                    __half* p = Cs + ((size_t)z * SEQ + s) * SK;
                    *(uint32_t*)(p + d)      = pack_h2(h0, h1);
                    *(uint32_t*)(p + 64 + d) = pack_h2(l0, l1);
                } else if (zk == 1) {    // K: [hi | hi]
                    __half* p = Cs + ((size_t)z * SEQ + s) * SK;
                    const uint32_t hh = pack_h2(h0, h1);
                    *(uint32_t*)(p + d)      = hh;
                    *(uint32_t*)(p + 64 + d) = hh;
                } else {                 // V^T: per-32-chunk [hi | hi]
                    const size_t b0 =
                        ((size_t)z * DHEAD + d) * VK + 64 * (s >> 5) + (s & 31);
                    Cs[b0]       = h0;
                    Cs[b0 + 32]  = h0;
                    const size_t b1 = b0 + VK;   // d+1 row
                    Cs[b1]       = h1;
                    Cs[b1 + 32]  = h1;
                }
            }
        }
    }
}

// ---------------------------------------------------------------------------
// Output projection: D[8192,1024] fp32 = ohs[8192,2048] x wos[1024,2048]^T + bias
// ---------------------------------------------------------------------------
__global__ __launch_bounds__(256) void proj_out(
    const __half* __restrict__ Ag, const __half* __restrict__ Bg,
    const float* __restrict__ bias, float* __restrict__ Cf)
{
    extern __shared__ char smem[];
    const int mbase = blockIdx.y * 128;
    const int nbase = blockIdx.x * 128;

    float acc[4][4][4];
#pragma unroll
    for (int i = 0; i < 4; i++)
#pragma unroll
        for (int j = 0; j < 4; j++)
#pragma unroll
            for (int r = 0; r < 4; r++) acc[i][j][r] = 0.0f;

    mma_loop_128x128<4>(smem, Ag + (size_t)mbase * GK, Bg + (size_t)nbase * GK,
                        GK, GK, GK / 32, acc);

    const int lane = threadIdx.x & 31;
    const int warp = threadIdx.x >> 5;
    const int wm = (warp >> 2) * 64;
    const int wn = (warp & 3) * 32;
    const int g = lane >> 2, tg = lane & 3;

#pragma unroll
    for (int mi = 0; mi < 4; ++mi) {
#pragma unroll
        for (int ni = 0; ni < 4; ++ni) {
#pragma unroll
            for (int half = 0; half < 2; ++half) {
                const int m = mbase + wm + mi * 16 + g + half * 8;
                const int n0 = nbase + wn + ni * 8 + tg * 2;
                float v0 = acc[mi][ni][half * 2 + 0] + bias[n0];
                float v1 = acc[mi][ni][half * 2 + 1] + bias[n0 + 1];
                *(float2*)&Cf[(size_t)m * DMODEL + n0] = make_float2(v0, v1);
            }
        }
    }
}

// ---------------------------------------------------------------------------
// Scores GEMM per head-slice z: writes e = exp(score) as FP16 to g_eh and
// per-row partial sums to psum[row][blockIdx.x]. 3 CTAs/SM target.
// ---------------------------------------------------------------------------
__global__ __launch_bounds__(256, 3) void scores_mma(
    const __half* __restrict__ qsp, const __half* __restrict__ ksp,
    __half* __restrict__ eh, float* __restrict__ psum)
{
    extern __shared__ char smem[];
    __shared__ float rowpart[4][128];
    const int z     = blockIdx.z;
    const int qbase = blockIdx.y * 128;
    const int kbase = blockIdx.x * 128;

    float acc[4][4][4];
#pragma unroll
    for (int i = 0; i < 4; i++)
#pragma unroll
        for (int j = 0; j < 4; j++)
#pragma unroll
            for (int r = 0; r < 4; r++) acc[i][j][r] = 0.0f;

    const __half* Abase = qsp + ((size_t)z * SEQ + qbase) * SK;
    const __half* Bbase = ksp + ((size_t)z * SEQ + kbase) * SK;
    mma_loop_128x128<3>(smem, Abase, Bbase, SK, SK, SK / 32, acc);

    const int lane = threadIdx.x & 31;
    const int warp = threadIdx.x >> 5;
    const int wm = (warp >> 2) * 64;
    const int wn = (warp & 3) * 32;
    const int g = lane >> 2, tg = lane & 3;

    __half* out = eh + ((size_t)z * SEQ + qbase) * SEQ + kbase;
#pragma unroll
    for (int mi = 0; mi < 4; ++mi) {
#pragma unroll
        for (int half = 0; half < 2; ++half) {
            const int r = wm + mi * 16 + g + half * 8;
            float s8 = 0.0f;
#pragma unroll
            for (int ni = 0; ni < 4; ++ni) {
                const int c = wn + ni * 8 + tg * 2;
                const __half h0 = __float2half_rn(__expf(acc[mi][ni][half * 2 + 0]));
                const __half h1 = __float2half_rn(__expf(acc[mi][ni][half * 2 + 1]));
                *(uint32_t*)&out[(size_t)r * SEQ + c] = pack_h2(h0, h1);
                s8 += __half2float(h0) + __half2float(h1);
            }
            s8 += __shfl_xor_sync(0xffffffffu, s8, 1);
            s8 += __shfl_xor_sync(0xffffffffu, s8, 2);
            if (tg == 0) rowpart[warp & 3][r] = s8;
        }
    }
    __syncthreads();
    if (threadIdx.x < 128) {
        const float s = (rowpart[0][threadIdx.x] + rowpart[1][threadIdx.x])
                      + (rowpart[2][threadIdx.x] + rowpart[3][threadIdx.x]);
        psum[((size_t)z * SEQ + qbase + threadIdx.x) * 16 + blockIdx.x] = s;
    }
}

// ---------------------------------------------------------------------------
// AV GEMM: per z: O[q,d] = sum_k P[q,k] V[k,d]. CTA 128x64, K_eff 4096.
// 3 CTAs/SM target.
// ---------------------------------------------------------------------------
#define AV_STAGE 30720u
#define AV_SMEM  (2 * 30720)

__global__ __launch_bounds__(256, 3) void av_mma(
    const __half* __restrict__ eh, float* __restrict__ attn,
    const float* __restrict__ psum,
    const __half* __restrict__ vsp, __half* __restrict__ ohs)
{
    extern __shared__ char smem[];
    const int z = blockIdx.y;
    const int mbase = blockIdx.x * 128;
    const int b = z >> 4, h = z & 15;
    const int tid = threadIdx.x, lane = tid & 31, warp = tid >> 5;
    const int wm = (warp >> 1) * 32, wn = (warp & 1) * 32;

    const __half* E = eh + ((size_t)z * SEQ + mbase) * SEQ;
    float* P = attn + ((size_t)z * SEQ + mbase) * SEQ;
    const __half* Vb = vsp + (size_t)z * DHEAD * VK;
    const float* ps = psum + ((size_t)z * SEQ + mbase) * 16;

    // per-thread rows: row_i = (tid + i*256)>>2, i in {0,1}
    float inv[2];
#pragma unroll
    for (int i = 0; i < 2; ++i) {
        const int row = (tid + i * 256) >> 2;
        const float* pr = ps + (size_t)row * 16;
        float s = 0.0f;
#pragma unroll
        for (int j = 0; j < 16; ++j) s += pr[j];
        inv[i] = 1.0f / s;
    }

    float acc[2][4][4];
#pragma unroll
    for (int i = 0; i < 2; i++)
#pragma unroll
        for (int j = 0; j < 4; j++)
#pragma unroll
            for (int r = 0; r < 4; r++) acc[i][j][r] = 0.0f;

    const uint32_t s0 = smem_u32(smem);
    const int mrow = lane & 15;
    const int kA = (lane & 16) ? 16 : 0;
    const int nr = (lane & 7) + ((lane & 16) ? 8 : 0);
    const int kB = (lane & 8) ? 16 : 0;

#define AV_ISSUE_V(gIt)                                                        \
    do {                                                                       \
        const uint32_t st = s0 + (uint32_t)((gIt) & 1) * AV_STAGE + 20480u;    \
        _Pragma("unroll")                                                      \
        for (int i = 0; i < 2; ++i) {                                          \
            const int idx = tid + i * 256;                                     \
            const int sub = idx >> 8, rem = idx & 255;                         \
            const int d = rem >> 2, jc = (rem & 3) * 8;                        \
            CP_ASYNC16(st + (uint32_t)(sub * 5120 + d * 80 + jc * 2),          \
                       Vb + (size_t)d * VK + (gIt) * 64 + sub * 32 + jc);      \
        }                                                                      \
        CP_COMMIT();                                                           \
    } while (0)

    AV_ISSUE_V(0);

    // e prefetch: 2 x uint4 (8 halves each) per thread
    uint4 pe[2];
#pragma unroll
    for (int i = 0; i < 2; ++i) {
        const int idx = tid + i * 256;
        const int row = idx >> 2, c8 = (idx & 3) * 8;
        pe[i] = *(const uint4*)&E[(size_t)row * SEQ + c8];
    }

    const int nIt = SEQ / 32;   // 64
    for (int it = 0; it < nIt; ++it) {
        const uint32_t stOff = (uint32_t)(it & 1) * AV_STAGE;
#pragma unroll
        for (int i = 0; i < 2; ++i) {
            const int idx = tid + i * 256;
            const int row = idx >> 2, c8 = (idx & 3) * 8;
            const __half2* eh2 = (const __half2*)&pe[i];
            float p[8];
#pragma unroll
            for (int j = 0; j < 4; ++j) {
                float2 f = __half22float2(eh2[j]);
                p[2 * j]     = f.x * inv[i];
                p[2 * j + 1] = f.y * inv[i];
            }
            // final normalized attn (fp32 output), streaming stores
            float* Pw = &P[(size_t)row * SEQ + it * 32 + c8];
            __stcs((float4*)(Pw),     make_float4(p[0], p[1], p[2], p[3]));
            __stcs((float4*)(Pw + 4), make_float4(p[4], p[5], p[6], p[7]));
            // split p -> [hi | lo]
            uint4 hp, lp;
            __half hh[8], ll[8];
#pragma unroll
            for (int j = 0; j < 8; ++j) {
                hh[j] = __float2half_rn(p[j]);
                ll[j] = __float2half_rn(p[j] - __half2float(hh[j]));
            }
            hp.x = pack_h2(hh[0], hh[1]); hp.y = pack_h2(hh[2], hh[3]);
            hp.z = pack_h2(hh[4], hh[5]); hp.w = pack_h2(hh[6], hh[7]);
            lp.x = pack_h2(ll[0], ll[1]); lp.y = pack_h2(ll[2], ll[3]);
            lp.z = pack_h2(ll[4], ll[5]); lp.w = pack_h2(ll[6], ll[7]);
            const uint32_t ro = (uint32_t)(row * 80 + c8 * 2);
            *(uint4*)(smem + stOff + ro)          = hp;   // sub 0: hi
            *(uint4*)(smem + stOff + 10240 + ro)  = lp;   // sub 1: lo
        }
        if (it + 1 < nIt) {
#pragma unroll
            for (int i = 0; i < 2; ++i) {
                const int idx = tid + i * 256;
                const int row = idx >> 2, c8 = (idx & 3) * 8;
                pe[i] = *(const uint4*)&E[(size_t)row * SEQ + (it + 1) * 32 + c8];
            }
        }
        CP_WAIT(0);
        __syncthreads();
        if (it + 1 < nIt) AV_ISSUE_V(it + 1);

#pragma unroll
        for (int sub = 0; sub < 2; ++sub) {
            const uint32_t aBase = s0 + stOff + (uint32_t)sub * 10240u;
            const uint32_t bBase = s0 + stOff + 20480u + (uint32_t)sub * 5120u;
#pragma unroll
            for (int ks = 0; ks < 2; ++ks) {
                uint32_t a[2][4], bq[4][2];
#pragma unroll
                for (int mi = 0; mi < 2; ++mi)
                    LDSM_X4(a[mi][0], a[mi][1], a[mi][2], a[mi][3],
                            aBase + (uint32_t)((wm + mi * 16 + mrow) * 80 + kA + ks * 32));
                LDSM_X4(bq[0][0], bq[0][1], bq[1][0], bq[1][1],
                        bBase + (uint32_t)((wn + nr) * 80 + kB + ks * 32));
                LDSM_X4(bq[2][0], bq[2][1], bq[3][0], bq[3][1],
                        bBase + (uint32_t)((wn + 16 + nr) * 80 + kB + ks * 32));
#pragma unroll
                for (int mi = 0; mi < 2; ++mi)
#pragma unroll
                    for (int ni = 0; ni < 4; ++ni)
                        MMA16816(acc[mi][ni], a[mi], bq[ni]);
            }
        }
    }
#undef AV_ISSUE_V

    // epilogue -> g_ohs [hi|lo]
    const int g = lane >> 2, tg = lane & 3;
#pragma unroll
    for (int mi = 0; mi < 2; ++mi) {
#pragma unroll
        for (int ni = 0; ni < 4; ++ni) {
#pragma unroll
            for (int half = 0; half < 2; ++half) {
                const int r = wm + mi * 16 + g + half * 8;
                const int c = wn + ni * 8 + tg * 2;
                const float v0 = acc[mi][ni][half * 2 + 0];
                const float v1 = acc[mi][ni][half * 2 + 1];
                const __half h0 = __float2half_rn(v0);
                const __half l0 = __float2half_rn(v0 - __half2float(h0));
                const __half h1 = __float2half_rn(v1);
                const __half l1 = __float2half_rn(v1 - __half2float(h1));
                const size_t row = (size_t)(b * SEQ + mbase + r);
                __half* p = ohs + row * GK + h * DHEAD + c;
                *(uint32_t*)p          = pack_h2(h0, h1);
                *(uint32_t*)(p + 1024) = pack_h2(l0, l1);
            }
        }
    }
}

// ---------------------------------------------------------------------------
// Merged prep_act: grid (total4/256, 3). X[R,1024] fp32 -> Y[R,2048] [hi|lo]
// ---------------------------------------------------------------------------
struct PrepActArgs { const float* X[3]; __half* Y[3]; };

__global__ __launch_bounds__(256) void prep_act3(PrepActArgs args)
{
    const float* X = args.X[blockIdx.y];
    __half* Y = args.Y[blockIdx.y];
    int i = blockIdx.x * 256 + threadIdx.x;
    float4 xv = ((const float4*)X)[i];
    int r = i >> 8;
    int k = (i & 255) * 4;
    __half* p = Y + (size_t)r * GK + k;

    float xs[4] = {xv.x, xv.y, xv.z, xv.w};
    __half hi[4], lo[4];
#pragma unroll
    for (int j = 0; j < 4; j++) {
        hi[j] = __float2half_rn(xs[j]);
        lo[j] = __float2half_rn(xs[j] - __half2float(hi[j]));
    }
    *(uint32_t*)(p)          = pack_h2(hi[0], hi[1]);
    *(uint32_t*)(p + 2)      = pack_h2(hi[2], hi[3]);
    *(uint32_t*)(p + 1024)   = pack_h2(lo[0], lo[1]);
    *(uint32_t*)(p + 1026)   = pack_h2(lo[2], lo[3]);
}

// ---------------------------------------------------------------------------
// Merged prep_wgt: grid (32, 32, 4). W[1024,1024] -> Ws[N=1024,2048] [hi|hi]
// ---------------------------------------------------------------------------
struct PrepWgtArgs { const float* W[4]; __half* Ws[4]; };

__global__ __launch_bounds__(256) void prep_wgt4(PrepWgtArgs args)
{
    const float* W = args.W[blockIdx.z];
    __half* Ws = args.Ws[blockIdx.z];
    __shared__ float t[32][33];
    const int k0 = blockIdx.y * 32, n0 = blockIdx.x * 32;
    const int tx = threadIdx.x, ty = threadIdx.y;   // (32, 8)
#pragma unroll
    for (int r = ty; r < 32; r += 8)
        t[r][tx] = W[(size_t)(k0 + r) * DMODEL + n0 + tx];
    __syncthreads();
#pragma unroll
    for (int r = ty; r < 32; r += 8) {
        const int n = n0 + r;
        const int k = k0 + tx;
        const __half hi = __float2half_rn(t[tx][r]);
        __half* p = Ws + (size_t)n * GK;
        p[k]        = hi;
        p[1024 + k] = hi;
    }
}

// ---------------------------------------------------------------------------
extern "C" void kernel_launch(void* const* d_in, const int* in_sizes, int n_in,
                              void* d_out, int out_size)
{
    const float* q  = (const float*)d_in[0];
    const float* k  = (const float*)d_in[1];
    const float* v  = (const float*)d_in[2];
    const float* Wq = (const float*)d_in[3];
    const float* bq = (const float*)d_in[4];
    const float* Wk = (const float*)d_in[5];
    const float* bk = (const float*)d_in[6];
    const float* Wv = (const float*)d_in[7];
    const float* bv = (const float*)d_in[8];
    const float* Wo = (const float*)d_in[9];
    const float* bo = (const float*)d_in[10];

    float* out  = (float*)d_out;
    float* attn = out + OUT_ELEMS;

    __half *qs, *ks, *vs, *ohs, *wqs, *wks, *wvs, *wos, *qsp, *ksp, *vsp, *ehp;
    float* psum;
    cudaGetSymbolAddress((void**)&qs,  g_qs);
    cudaGetSymbolAddress((void**)&ks,  g_ks);
    cudaGetSymbolAddress((void**)&vs,  g_vs);
    cudaGetSymbolAddress((void**)&ohs, g_ohs);
    cudaGetSymbolAddress((void**)&wqs, g_wqs);
    cudaGetSymbolAddress((void**)&wks, g_wks);
    cudaGetSymbolAddress((void**)&wvs, g_wvs);
    cudaGetSymbolAddress((void**)&wos, g_wos);
    cudaGetSymbolAddress((void**)&qsp, g_qsp);
    cudaGetSymbolAddress((void**)&ksp, g_ksp);
    cudaGetSymbolAddress((void**)&vsp, g_vsp);
    cudaGetSymbolAddress((void**)&ehp, g_eh);
    cudaGetSymbolAddress((void**)&psum, g_psum);

    cudaFuncSetAttribute(proj_qkv,   cudaFuncAttributeMaxDynamicSharedMemorySize, MAIN_SMEM);
    cudaFuncSetAttribute(proj_out,   cudaFuncAttributeMaxDynamicSharedMemorySize, MAIN_SMEM);
    cudaFuncSetAttribute(scores_mma, cudaFuncAttributeMaxDynamicSharedMemorySize, SC_SMEM);
    cudaFuncSetAttribute(av_mma,     cudaFuncAttributeMaxDynamicSharedMemorySize, AV_SMEM);

    const int act4 = MROWS * DMODEL / 4;   // 2097152 -> 8192 blocks

    // 0) fp16 2-term conversions (merged launches)
    PrepWgtArgs wargs;
    wargs.W[0] = Wq; wargs.W[1] = Wk; wargs.W[2] = Wv; wargs.W[3] = Wo;
    wargs.Ws[0] = wqs; wargs.Ws[1] = wks; wargs.Ws[2] = wvs; wargs.Ws[3] = wos;
    prep_wgt4<<<dim3(32, 32, 4), dim3(32, 8)>>>(wargs);

    PrepActArgs aargs;
    aargs.X[0] = q; aargs.X[1] = k; aargs.X[2] = v;
    aargs.Y[0] = qs; aargs.Y[1] = ks; aargs.Y[2] = vs;
    prep_act3<<<dim3(act4 / 256, 3), 256>>>(aargs);

    // 1) Q/K/V projections merged (HMMA): grid (8, 64, 3)
    QKVArgs pargs;
    pargs.A[0] = qs;  pargs.A[1] = ks;  pargs.A[2] = vs;
    pargs.W[0] = wqs; pargs.W[1] = wks; pargs.W[2] = wvs;
    pargs.bias[0] = bq; pargs.bias[1] = bk; pargs.bias[2] = bv;
    pargs.C[0] = qsp; pargs.C[1] = ksp; pargs.C[2] = vsp;
    proj_qkv<<<dim3(DMODEL / 128, MROWS / 128, 3), 256, MAIN_SMEM>>>(pargs);

    // 2) Scores -> e = exp(score) fp16 into g_eh + per-row partial sums
    dim3 gs(SEQ / 128, SEQ / 128, NZ);  // (16, 16, 64)
    scores_mma<<<gs, 256, SC_SMEM>>>(qsp, ksp, ehp, psum);

    // 3) AV: normalize, write final attn fp32 (streaming), O -> g_ohs [hi|lo]
    dim3 ga(SEQ / 128, NZ);  // (16, 64)
    av_mma<<<ga, 256, AV_SMEM>>>(ehp, attn, psum, vsp, ohs);

    // 4) Output projection -> d_out
    proj_out<<<dim3(DMODEL / 128, MROWS / 128), 256, MAIN_SMEM>>>(ohs, wos, bo, out);
}

// round 15
// speedup vs baseline: 1.2760x; 1.2760x over previous
#include <cuda_runtime.h>
#include <cuda_fp16.h>
#include <cstdint>

// Problem constants
#define BATCH 4
#define SEQ   2048
#define DMODEL 1024
#define NHEAD 16
#define DHEAD 64
#define MROWS (BATCH * SEQ)                       // 8192
#define OUT_ELEMS ((size_t)BATCH * SEQ * DMODEL)  // 8388608
#define GK 2048                                   // fp16 2-term K (2 x 1024)
#define SK 64                                     // scores K (single fp16)
#define NZ (BATCH * NHEAD)                        // 64 head-slices
#define VK 2048                                   // AV K (single fp16)

// ---------------------------------------------------------------------------
// Scratch (device globals; allocation-free rule)
// ---------------------------------------------------------------------------
__device__ __half g_qs [(size_t)MROWS * GK];    // activations [hi | lo]
__device__ __half g_ks [(size_t)MROWS * GK];
__device__ __half g_vs [(size_t)MROWS * GK];
__device__ __half g_ohs[(size_t)MROWS * GK];
__device__ __half g_wqs[(size_t)DMODEL * GK];   // weights^T [hi | hi]
__device__ __half g_wks[(size_t)DMODEL * GK];
__device__ __half g_wvs[(size_t)DMODEL * GK];
__device__ __half g_wos[(size_t)DMODEL * GK];
__device__ __half g_qsp[(size_t)NZ * SEQ * SK]; // Q heads fp16, pre-scaled 0.125
__device__ __half g_ksp[(size_t)NZ * SEQ * SK]; // K heads fp16
__device__ __half g_vsp[(size_t)NZ * DHEAD * VK]; // V^T fp16 [z][d][s]
__device__ __half g_eh [(size_t)NZ * SEQ * SEQ]; // unnormalized exp(score), fp16
__device__ float g_psum[(size_t)NZ * SEQ * 16];

// ---------------------------------------------------------------------------
// MMA / async-copy helpers
// ---------------------------------------------------------------------------
__device__ __forceinline__ uint32_t smem_u32(const void* p) {
    uint32_t a;
    asm("{ .reg .u64 t; cvta.to.shared.u64 t, %1; cvt.u32.u64 %0, t; }"
        : "=r"(a) : "l"(p));
    return a;
}

#define LDSM_X4(r0, r1, r2, r3, addr)                                          \
    asm volatile("ldmatrix.sync.aligned.m8n8.x4.shared.b16 {%0,%1,%2,%3}, [%4];" \
                 : "=r"(r0), "=r"(r1), "=r"(r2), "=r"(r3) : "r"(addr))

#define MMA16816(d, a, b)                                                      \
    asm volatile("mma.sync.aligned.m16n8k16.row.col.f32.f16.f16.f32 "          \
                 "{%0,%1,%2,%3}, {%4,%5,%6,%7}, {%8,%9}, {%0,%1,%2,%3};"       \
                 : "+f"((d)[0]), "+f"((d)[1]), "+f"((d)[2]), "+f"((d)[3])      \
                 : "r"((a)[0]), "r"((a)[1]), "r"((a)[2]), "r"((a)[3]),         \
                   "r"((b)[0]), "r"((b)[1]))

#define CP_ASYNC16(dst, src)                                                   \
    asm volatile("cp.async.cg.shared.global [%0], [%1], 16;"                   \
                 :: "r"(dst), "l"(src))
#define CP_COMMIT() asm volatile("cp.async.commit_group;" ::: "memory")
#define CP_WAIT(n)  asm volatile("cp.async.wait_group %0;" :: "n"(n) : "memory")

__device__ __forceinline__ uint32_t pack_h2(__half a, __half b) {
    __half2 h = __halves2half2(a, b);
    return *(uint32_t*)&h;
}

// One pipeline stage: A[128][40] then B[128][40] halves (80 B row stride).
#define TSTAGE 20480u
#define MAIN_SMEM (4 * 20480)     // proj: 4-stage
#define SC_SMEM  (3 * 20480)      // scores: 3-stage (only 2 iters)

// Core loop: CTA 128x128, 8 warps (2Mx4N), K-step 32,
// STAGES-deep cp.async pipeline. nIters >= STAGES-1 not required
// (prologue issues only existing tiles when nIters < STAGES-1 is impossible
// here; nIters >= 2 in all uses).
template <int STAGES>
__device__ __forceinline__ void mma_loop_128x128(
    char* smem, const __half* __restrict__ Abase,
    const __half* __restrict__ Bbase,
    int lda, int ldb, int nIters, float acc[4][4][4])
{
    const int tid  = threadIdx.x;
    const int lane = tid & 31;
    const int warp = tid >> 5;
    const int wm = (warp >> 2) * 64;
    const int wn = (warp & 3) * 32;

    const int grow = tid >> 2;
    const int gcol = (tid & 3) * 8;
    const __half* Ap = Abase + (size_t)grow * lda + gcol;
    const __half* Bp = Bbase + (size_t)grow * ldb + gcol;

    const uint32_t s0 = smem_u32(smem);
    const uint32_t aStOff = (uint32_t)(grow * 80 + gcol * 2);
    const uint32_t bStOff = 10240u + (uint32_t)(grow * 80 + gcol * 2);

    const int mrow  = lane & 15;
    const int kA    = (lane & 16) ? 16 : 0;
    const int nrow  = (lane & 7) + ((lane & 16) ? 8 : 0);
    const int kB    = (lane & 8) ? 16 : 0;
    const uint32_t aLdm = s0 + (uint32_t)((wm + mrow) * 80 + kA);
    const uint32_t bLdm = s0 + 10240u + (uint32_t)((wn + nrow) * 80 + kB);

#define ISSUE_TILE(g)                                                          \
    do {                                                                       \
        const uint32_t st = s0 + (uint32_t)((g) % STAGES) * TSTAGE;            \
        const __half* An = Ap + (g) * 32;                                      \
        const __half* Bn = Bp + (g) * 32;                                      \
        CP_ASYNC16(st + aStOff, An);                                           \
        CP_ASYNC16(st + aStOff + 64u * 80u, An + (size_t)64 * lda);            \
        CP_ASYNC16(st + bStOff, Bn);                                           \
        CP_ASYNC16(st + bStOff + 64u * 80u, Bn + (size_t)64 * ldb);            \
        CP_COMMIT();                                                           \
    } while (0)

#pragma unroll
    for (int p = 0; p < STAGES - 1; ++p) ISSUE_TILE(p);

    for (int it = 0; it < nIters; ++it) {
        const int rem = nIters - 1 - it;   // tiles after this one
        if (STAGES >= 4 && rem >= 2)      { CP_WAIT(2); }
        else if (rem >= 1)                { CP_WAIT(1); }
        else                              { CP_WAIT(0); }
        __syncthreads();
        if (it + STAGES - 1 < nIters) ISSUE_TILE(it + STAGES - 1);

        const uint32_t cur = (uint32_t)(it % STAGES) * TSTAGE;
#pragma unroll
        for (int ks = 0; ks < 2; ++ks) {
            uint32_t a[4][4], b[4][2];
#pragma unroll
            for (int mi = 0; mi < 4; ++mi)
                LDSM_X4(a[mi][0], a[mi][1], a[mi][2], a[mi][3],
                        aLdm + cur + (uint32_t)(mi * 16 * 80 + ks * 32));
            LDSM_X4(b[0][0], b[0][1], b[1][0], b[1][1],
                    bLdm + cur + (uint32_t)(ks * 32));
            LDSM_X4(b[2][0], b[2][1], b[3][0], b[3][1],
                    bLdm + cur + (uint32_t)(16 * 80 + ks * 32));
#pragma unroll
            for (int mi = 0; mi < 4; ++mi)
#pragma unroll
                for (int ni = 0; ni < 4; ++ni)
                    MMA16816(acc[mi][ni], a[mi], b[ni]);
        }
    }
#undef ISSUE_TILE
}

// ---------------------------------------------------------------------------
// Merged Q/K/V projection: grid (8, 64, 3). z=0:Q, z=1:K, z=2:V.
// ---------------------------------------------------------------------------
struct QKVArgs {
    const __half* A[3];
    const __half* W[3];
    const float*  bias[3];
    __half*       C[3];
};

__global__ __launch_bounds__(256) void proj_qkv(QKVArgs args)
{
    extern __shared__ char smem[];
    const int zk = blockIdx.z;       // 0=Q, 1=K, 2=V
    const int mbase = blockIdx.y * 128;
    const int nbase = blockIdx.x * 128;

    const __half* Ag = args.A[zk];
    const __half* Bg = args.W[zk];
    const float* bias = args.bias[zk];
    __half* Cs = args.C[zk];

    float acc[4][4][4];
#pragma unroll
    for (int i = 0; i < 4; i++)
#pragma unroll
        for (int j = 0; j < 4; j++)
#pragma unroll
            for (int r = 0; r < 4; r++) acc[i][j][r] = 0.0f;

    mma_loop_128x128<4>(smem, Ag + (size_t)mbase * GK, Bg + (size_t)nbase * GK,
                        GK, GK, GK / 32, acc);

    const int lane = threadIdx.x & 31;
    const int warp = threadIdx.x >> 5;
    const int wm = (warp >> 2) * 64;
    const int wn = (warp & 3) * 32;
    const int g = lane >> 2, tg = lane & 3;

#pragma unroll
    for (int mi = 0; mi < 4; ++mi) {
#pragma unroll
        for (int ni = 0; ni < 4; ++ni) {
#pragma unroll
            for (int half = 0; half < 2; ++half) {
                const int m = mbase + wm + mi * 16 + g + half * 8;
                const int n0 = nbase + wn + ni * 8 + tg * 2;
                float v0 = acc[mi][ni][half * 2 + 0] + bias[n0];
                float v1 = acc[mi][ni][half * 2 + 1] + bias[n0 + 1];
                const int z = ((m >> 11) << 4) + (n0 >> 6);
                const int s = m & (SEQ - 1);
                const int d = n0 & 63;
                if (zk == 0) { v0 *= 0.125f; v1 *= 0.125f; }
                const __half h0 = __float2half_rn(v0);
                const __half h1 = __float2half_rn(v1);
                if (zk == 0 || zk == 1) {   // Q/K heads: single fp16 [z,s,64]
                    __half* p = Cs + ((size_t)z * SEQ + s) * SK;
                    *(uint32_t*)(p + d) = pack_h2(h0, h1);
                } else {                    // V^T fp16 [z][d][s]
                    const size_t b0 = ((size_t)z * DHEAD + d) * VK + s;
                    Cs[b0]      = h0;
                    Cs[b0 + VK] = h1;       // d+1 row
                }
            }
        }
    }
}

// ---------------------------------------------------------------------------
// Output projection: D[8192,1024] fp32 = ohs[8192,2048] x wos[1024,2048]^T + bias
// ---------------------------------------------------------------------------
__global__ __launch_bounds__(256) void proj_out(
    const __half* __restrict__ Ag, const __half* __restrict__ Bg,
    const float* __restrict__ bias, float* __restrict__ Cf)
{
    extern __shared__ char smem[];
    const int mbase = blockIdx.y * 128;
    const int nbase = blockIdx.x * 128;

    float acc[4][4][4];
#pragma unroll
    for (int i = 0; i < 4; i++)
#pragma unroll
        for (int j = 0; j < 4; j++)
#pragma unroll
            for (int r = 0; r < 4; r++) acc[i][j][r] = 0.0f;

    mma_loop_128x128<4>(smem, Ag + (size_t)mbase * GK, Bg + (size_t)nbase * GK,
                        GK, GK, GK / 32, acc);

    const int lane = threadIdx.x & 31;
    const int warp = threadIdx.x >> 5;
    const int wm = (warp >> 2) * 64;
    const int wn = (warp & 3) * 32;
    const int g = lane >> 2, tg = lane & 3;

#pragma unroll
    for (int mi = 0; mi < 4; ++mi) {
#pragma unroll
        for (int ni = 0; ni < 4; ++ni) {
#pragma unroll
            for (int half = 0; half < 2; ++half) {
                const int m = mbase + wm + mi * 16 + g + half * 8;
                const int n0 = nbase + wn + ni * 8 + tg * 2;
                float v0 = acc[mi][ni][half * 2 + 0] + bias[n0];
                float v1 = acc[mi][ni][half * 2 + 1] + bias[n0 + 1];
                *(float2*)&Cf[(size_t)m * DMODEL + n0] = make_float2(v0, v1);
            }
        }
    }
}

// ---------------------------------------------------------------------------
// Scores GEMM per head-slice z (K=64, single fp16): writes e = exp(score)
// fp16 to g_eh and per-row partial sums to psum[row][blockIdx.x].
// ---------------------------------------------------------------------------
__global__ __launch_bounds__(256) void scores_mma(
    const __half* __restrict__ qsp, const __half* __restrict__ ksp,
    __half* __restrict__ eh, float* __restrict__ psum)
{
    extern __shared__ char smem[];
    __shared__ float rowpart[4][128];
    const int z     = blockIdx.z;
    const int qbase = blockIdx.y * 128;
    const int kbase = blockIdx.x * 128;

    float acc[4][4][4];
#pragma unroll
    for (int i = 0; i < 4; i++)
#pragma unroll
        for (int j = 0; j < 4; j++)
#pragma unroll
            for (int r = 0; r < 4; r++) acc[i][j][r] = 0.0f;

    const __half* Abase = qsp + ((size_t)z * SEQ + qbase) * SK;
    const __half* Bbase = ksp + ((size_t)z * SEQ + kbase) * SK;
    mma_loop_128x128<3>(smem, Abase, Bbase, SK, SK, SK / 32, acc);

    const int lane = threadIdx.x & 31;
    const int warp = threadIdx.x >> 5;
    const int wm = (warp >> 2) * 64;
    const int wn = (warp & 3) * 32;
    const int g = lane >> 2, tg = lane & 3;

    __half* out = eh + ((size_t)z * SEQ + qbase) * SEQ + kbase;
#pragma unroll
    for (int mi = 0; mi < 4; ++mi) {
#pragma unroll
        for (int half = 0; half < 2; ++half) {
            const int r = wm + mi * 16 + g + half * 8;
            float s8 = 0.0f;
#pragma unroll
            for (int ni = 0; ni < 4; ++ni) {
                const int c = wn + ni * 8 + tg * 2;
                const __half h0 = __float2half_rn(__expf(acc[mi][ni][half * 2 + 0]));
                const __half h1 = __float2half_rn(__expf(acc[mi][ni][half * 2 + 1]));
                *(uint32_t*)&out[(size_t)r * SEQ + c] = pack_h2(h0, h1);
                s8 += __half2float(h0) + __half2float(h1);
            }
            s8 += __shfl_xor_sync(0xffffffffu, s8, 1);
            s8 += __shfl_xor_sync(0xffffffffu, s8, 2);
            if (tg == 0) rowpart[warp & 3][r] = s8;
        }
    }
    __syncthreads();
    if (threadIdx.x < 128) {
        const float s = (rowpart[0][threadIdx.x] + rowpart[1][threadIdx.x])
                      + (rowpart[2][threadIdx.x] + rowpart[3][threadIdx.x]);
        psum[((size_t)z * SEQ + qbase + threadIdx.x) * 16 + blockIdx.x] = s;
    }
}

// ---------------------------------------------------------------------------
// AV GEMM (single fp16 p and V): per z: O[q,d] = sum_k p[q,k] V[k,d].
// CTA 128x64, K_eff = 2048. Stage = A(10240) + B(5120) = 15360 B.
// ---------------------------------------------------------------------------
#define AV_STAGE 15360u
#define AV_SMEM  (2 * 15360)

__global__ __launch_bounds__(256) void av_mma(
    const __half* __restrict__ eh, float* __restrict__ attn,
    const float* __restrict__ psum,
    const __half* __restrict__ vsp, __half* __restrict__ ohs)
{
    extern __shared__ char smem[];
    const int z = blockIdx.y;
    const int mbase = blockIdx.x * 128;
    const int b = z >> 4, h = z & 15;
    const int tid = threadIdx.x, lane = tid & 31, warp = tid >> 5;
    const int wm = (warp >> 1) * 32, wn = (warp & 1) * 32;

    const __half* E = eh + ((size_t)z * SEQ + mbase) * SEQ;
    float* P = attn + ((size_t)z * SEQ + mbase) * SEQ;
    const __half* Vb = vsp + (size_t)z * DHEAD * VK;
    const float* ps = psum + ((size_t)z * SEQ + mbase) * 16;

    // per-thread rows: row_i = (tid + i*256)>>2, i in {0,1}
    float inv[2];
#pragma unroll
    for (int i = 0; i < 2; ++i) {
        const int row = (tid + i * 256) >> 2;
        const float* pr = ps + (size_t)row * 16;
        float s = 0.0f;
#pragma unroll
        for (int j = 0; j < 16; ++j) s += pr[j];
        inv[i] = 1.0f / s;
    }

    float acc[2][4][4];
#pragma unroll
    for (int i = 0; i < 2; i++)
#pragma unroll
        for (int j = 0; j < 4; j++)
#pragma unroll
            for (int r = 0; r < 4; r++) acc[i][j][r] = 0.0f;

    const uint32_t s0 = smem_u32(smem);
    const int mrow = lane & 15;
    const int kA = (lane & 16) ? 16 : 0;
    const int nr = (lane & 7) + ((lane & 16) ? 8 : 0);
    const int kB = (lane & 8) ? 16 : 0;

    // V issue: 256 x 16B chunks per stage, 1 per thread
#define AV_ISSUE_V(gIt)                                                        \
    do {                                                                       \
        const uint32_t st = s0 + (uint32_t)((gIt) & 1) * AV_STAGE + 10240u;    \
        const int d = tid >> 2, jc = (tid & 3) * 8;                            \
        CP_ASYNC16(st + (uint32_t)(d * 80 + jc * 2),                           \
                   Vb + (size_t)d * VK + (gIt) * 32 + jc);                     \
        CP_COMMIT();                                                           \
    } while (0)

    AV_ISSUE_V(0);

    // e prefetch: 2 x uint4 (8 halves each) per thread
    uint4 pe[2];
#pragma unroll
    for (int i = 0; i < 2; ++i) {
        const int idx = tid + i * 256;
        const int row = idx >> 2, c8 = (idx & 3) * 8;
        pe[i] = *(const uint4*)&E[(size_t)row * SEQ + c8];
    }

    const int nIt = SEQ / 32;   // 64
    for (int it = 0; it < nIt; ++it) {
        const uint32_t stOff = (uint32_t)(it & 1) * AV_STAGE;
#pragma unroll
        for (int i = 0; i < 2; ++i) {
            const int idx = tid + i * 256;
            const int row = idx >> 2, c8 = (idx & 3) * 8;
            const __half2* eh2 = (const __half2*)&pe[i];
            float p[8];
#pragma unroll
            for (int j = 0; j < 4; ++j) {
                float2 f = __half22float2(eh2[j]);
                p[2 * j]     = f.x * inv[i];
                p[2 * j + 1] = f.y * inv[i];
            }
            // final normalized attn (fp32 output), streaming stores
            float* Pw = &P[(size_t)row * SEQ + it * 32 + c8];
            __stcs((float4*)(Pw),     make_float4(p[0], p[1], p[2], p[3]));
            __stcs((float4*)(Pw + 4), make_float4(p[4], p[5], p[6], p[7]));
            // p -> fp16 smem (single term)
            uint4 hp;
            __half hh[8];
#pragma unroll
            for (int j = 0; j < 8; ++j) hh[j] = __float2half_rn(p[j]);
            hp.x = pack_h2(hh[0], hh[1]); hp.y = pack_h2(hh[2], hh[3]);
            hp.z = pack_h2(hh[4], hh[5]); hp.w = pack_h2(hh[6], hh[7]);
            *(uint4*)(smem + stOff + (uint32_t)(row * 80 + c8 * 2)) = hp;
        }
        if (it + 1 < nIt) {
#pragma unroll
            for (int i = 0; i < 2; ++i) {
                const int idx = tid + i * 256;
                const int row = idx >> 2, c8 = (idx & 3) * 8;
                pe[i] = *(const uint4*)&E[(size_t)row * SEQ + (it + 1) * 32 + c8];
            }
        }
        CP_WAIT(0);
        __syncthreads();
        if (it + 1 < nIt) AV_ISSUE_V(it + 1);

        const uint32_t aBase = s0 + stOff;
        const uint32_t bBase = s0 + stOff + 10240u;
#pragma unroll
        for (int ks = 0; ks < 2; ++ks) {
            uint32_t a[2][4], bq[4][2];
#pragma unroll
            for (int mi = 0; mi < 2; ++mi)
                LDSM_X4(a[mi][0], a[mi][1], a[mi][2], a[mi][3],
                        aBase + (uint32_t)((wm + mi * 16 + mrow) * 80 + kA + ks * 32));
            LDSM_X4(bq[0][0], bq[0][1], bq[1][0], bq[1][1],
                    bBase + (uint32_t)((wn + nr) * 80 + kB + ks * 32));
            LDSM_X4(bq[2][0], bq[2][1], bq[3][0], bq[3][1],
                    bBase + (uint32_t)((wn + 16 + nr) * 80 + kB + ks * 32));
#pragma unroll
            for (int mi = 0; mi < 2; ++mi)
#pragma unroll
                for (int ni = 0; ni < 4; ++ni)
                    MMA16816(acc[mi][ni], a[mi], bq[ni]);
        }
    }
#undef AV_ISSUE_V

    // epilogue -> g_ohs [hi|lo]
    const int g = lane >> 2, tg = lane & 3;
#pragma unroll
    for (int mi = 0; mi < 2; ++mi) {
#pragma unroll
        for (int ni = 0; ni < 4; ++ni) {
#pragma unroll
            for (int half = 0; half < 2; ++half) {
                const int r = wm + mi * 16 + g + half * 8;
                const int c = wn + ni * 8 + tg * 2;
                const float v0 = acc[mi][ni][half * 2 + 0];
                const float v1 = acc[mi][ni][half * 2 + 1];
                const __half h0 = __float2half_rn(v0);
                const __half l0 = __float2half_rn(v0 - __half2float(h0));
                const __half h1 = __float2half_rn(v1);
                const __half l1 = __float2half_rn(v1 - __half2float(h1));
                const size_t row = (size_t)(b * SEQ + mbase + r);
                __half* p = ohs + row * GK + h * DHEAD + c;
                *(uint32_t*)p          = pack_h2(h0, h1);
                *(uint32_t*)(p + 1024) = pack_h2(l0, l1);
            }
        }
    }
}

// ---------------------------------------------------------------------------
// Merged prep_act: grid (total4/256, 3). X[R,1024] fp32 -> Y[R,2048] [hi|lo]
// ---------------------------------------------------------------------------
struct PrepActArgs { const float* X[3]; __half* Y[3]; };

__global__ __launch_bounds__(256) void prep_act3(PrepActArgs args)
{
    const float* X = args.X[blockIdx.y];
    __half* Y = args.Y[blockIdx.y];
    int i = blockIdx.x * 256 + threadIdx.x;
    float4 xv = ((const float4*)X)[i];
    int r = i >> 8;
    int k = (i & 255) * 4;
    __half* p = Y + (size_t)r * GK + k;

    float xs[4] = {xv.x, xv.y, xv.z, xv.w};
    __half hi[4], lo[4];
#pragma unroll
    for (int j = 0; j < 4; j++) {
        hi[j] = __float2half_rn(xs[j]);
        lo[j] = __float2half_rn(xs[j] - __half2float(hi[j]));
    }
    *(uint32_t*)(p)          = pack_h2(hi[0], hi[1]);
    *(uint32_t*)(p + 2)      = pack_h2(hi[2], hi[3]);
    *(uint32_t*)(p + 1024)   = pack_h2(lo[0], lo[1]);
    *(uint32_t*)(p + 1026)   = pack_h2(lo[2], lo[3]);
}

// ---------------------------------------------------------------------------
// Merged prep_wgt: grid (32, 32, 4). W[1024,1024] -> Ws[N=1024,2048] [hi|hi]
// ---------------------------------------------------------------------------
struct PrepWgtArgs { const float* W[4]; __half* Ws[4]; };

__global__ __launch_bounds__(256) void prep_wgt4(PrepWgtArgs args)
{
    const float* W = args.W[blockIdx.z];
    __half* Ws = args.Ws[blockIdx.z];
    __shared__ float t[32][33];
    const int k0 = blockIdx.y * 32, n0 = blockIdx.x * 32;
    const int tx = threadIdx.x, ty = threadIdx.y;   // (32, 8)
#pragma unroll
    for (int r = ty; r < 32; r += 8)
        t[r][tx] = W[(size_t)(k0 + r) * DMODEL + n0 + tx];
    __syncthreads();
#pragma unroll
    for (int r = ty; r < 32; r += 8) {
        const int n = n0 + r;
        const int k = k0 + tx;
        const __half hi = __float2half_rn(t[tx][r]);
        __half* p = Ws + (size_t)n * GK;
        p[k]        = hi;
        p[1024 + k] = hi;
    }
}

// ---------------------------------------------------------------------------
extern "C" void kernel_launch(void* const* d_in, const int* in_sizes, int n_in,
                              void* d_out, int out_size)
{
    const float* q  = (const float*)d_in[0];
    const float* k  = (const float*)d_in[1];
    const float* v  = (const float*)d_in[2];
    const float* Wq = (const float*)d_in[3];
    const float* bq = (const float*)d_in[4];
    const float* Wk = (const float*)d_in[5];
    const float* bk = (const float*)d_in[6];
    const float* Wv = (const float*)d_in[7];
    const float* bv = (const float*)d_in[8];
    const float* Wo = (const float*)d_in[9];
    const float* bo = (const float*)d_in[10];

    float* out  = (float*)d_out;
    float* attn = out + OUT_ELEMS;

    __half *qs, *ks, *vs, *ohs, *wqs, *wks, *wvs, *wos, *qsp, *ksp, *vsp, *ehp;
    float* psum;
    cudaGetSymbolAddress((void**)&qs,  g_qs);
    cudaGetSymbolAddress((void**)&ks,  g_ks);
    cudaGetSymbolAddress((void**)&vs,  g_vs);
    cudaGetSymbolAddress((void**)&ohs, g_ohs);
    cudaGetSymbolAddress((void**)&wqs, g_wqs);
    cudaGetSymbolAddress((void**)&wks, g_wks);
    cudaGetSymbolAddress((void**)&wvs, g_wvs);
    cudaGetSymbolAddress((void**)&wos, g_wos);
    cudaGetSymbolAddress((void**)&qsp, g_qsp);
    cudaGetSymbolAddress((void**)&ksp, g_ksp);
    cudaGetSymbolAddress((void**)&vsp, g_vsp);
    cudaGetSymbolAddress((void**)&ehp, g_eh);
    cudaGetSymbolAddress((void**)&psum, g_psum);

    cudaFuncSetAttribute(proj_qkv,   cudaFuncAttributeMaxDynamicSharedMemorySize, MAIN_SMEM);
    cudaFuncSetAttribute(proj_out,   cudaFuncAttributeMaxDynamicSharedMemorySize, MAIN_SMEM);
    cudaFuncSetAttribute(scores_mma, cudaFuncAttributeMaxDynamicSharedMemorySize, SC_SMEM);
    cudaFuncSetAttribute(av_mma,     cudaFuncAttributeMaxDynamicSharedMemorySize, AV_SMEM);

    const int act4 = MROWS * DMODEL / 4;   // 2097152 -> 8192 blocks

    // 0) fp16 2-term conversions (merged launches)
    PrepWgtArgs wargs;
    wargs.W[0] = Wq; wargs.W[1] = Wk; wargs.W[2] = Wv; wargs.W[3] = Wo;
    wargs.Ws[0] = wqs; wargs.Ws[1] = wks; wargs.Ws[2] = wvs; wargs.Ws[3] = wos;
    prep_wgt4<<<dim3(32, 32, 4), dim3(32, 8)>>>(wargs);

    PrepActArgs aargs;
    aargs.X[0] = q; aargs.X[1] = k; aargs.X[2] = v;
    aargs.Y[0] = qs; aargs.Y[1] = ks; aargs.Y[2] = vs;
    prep_act3<<<dim3(act4 / 256, 3), 256>>>(aargs);

    // 1) Q/K/V projections merged (HMMA): grid (8, 64, 3)
    QKVArgs pargs;
    pargs.A[0] = qs;  pargs.A[1] = ks;  pargs.A[2] = vs;
    pargs.W[0] = wqs; pargs.W[1] = wks; pargs.W[2] = wvs;
    pargs.bias[0] = bq; pargs.bias[1] = bk; pargs.bias[2] = bv;
    pargs.C[0] = qsp; pargs.C[1] = ksp; pargs.C[2] = vsp;
    proj_qkv<<<dim3(DMODEL / 128, MROWS / 128, 3), 256, MAIN_SMEM>>>(pargs);

    // 2) Scores (K=64) -> e = exp(score) fp16 into g_eh + row partial sums
    dim3 gs(SEQ / 128, SEQ / 128, NZ);  // (16, 16, 64)
    scores_mma<<<gs, 256, SC_SMEM>>>(qsp, ksp, ehp, psum);

    // 3) AV (K=2048 single): normalize, write attn fp32, O -> g_ohs [hi|lo]
    dim3 ga(SEQ / 128, NZ);  // (16, 64)
    av_mma<<<ga, 256, AV_SMEM>>>(ehp, attn, psum, vsp, ohs);

    // 4) Output projection -> d_out
    proj_out<<<dim3(DMODEL / 128, MROWS / 128), 256, MAIN_SMEM>>>(ohs, wos, bo, out);
}

// round 16
// speedup vs baseline: 1.5537x; 1.2176x over previous
#include <cuda_runtime.h>
#include <cuda_fp16.h>
#include <cstdint>

// Problem constants
#define BATCH 4
#define SEQ   2048
#define DMODEL 1024
#define NHEAD 16
#define DHEAD 64
#define MROWS (BATCH * SEQ)                       // 8192
#define OUT_ELEMS ((size_t)BATCH * SEQ * DMODEL)  // 8388608
#define GK 1024                                   // plain fp16 K
#define SK 64                                     // scores K (single fp16)
#define NZ (BATCH * NHEAD)                        // 64 head-slices
#define VK 2048                                   // AV K (single fp16)

// ---------------------------------------------------------------------------
// Scratch (device globals; allocation-free rule)
// ---------------------------------------------------------------------------
__device__ __half g_qs [(size_t)MROWS * GK];    // activations fp16
__device__ __half g_ks [(size_t)MROWS * GK];
__device__ __half g_vs [(size_t)MROWS * GK];
__device__ __half g_ohs[(size_t)MROWS * GK];
__device__ __half g_wqs[(size_t)DMODEL * GK];   // weights^T fp16
__device__ __half g_wks[(size_t)DMODEL * GK];
__device__ __half g_wvs[(size_t)DMODEL * GK];
__device__ __half g_wos[(size_t)DMODEL * GK];
__device__ __half g_qsp[(size_t)NZ * SEQ * SK]; // Q heads fp16, pre-scaled 0.125
__device__ __half g_ksp[(size_t)NZ * SEQ * SK]; // K heads fp16
__device__ __half g_vsp[(size_t)NZ * DHEAD * VK]; // V^T fp16 [z][d][s]
__device__ __half g_eh [(size_t)NZ * SEQ * SEQ]; // unnormalized exp(score), fp16
__device__ float g_psum[(size_t)NZ * SEQ * 16];

// ---------------------------------------------------------------------------
// MMA / async-copy helpers
// ---------------------------------------------------------------------------
__device__ __forceinline__ uint32_t smem_u32(const void* p) {
    uint32_t a;
    asm("{ .reg .u64 t; cvta.to.shared.u64 t, %1; cvt.u32.u64 %0, t; }"
        : "=r"(a) : "l"(p));
    return a;
}

#define LDSM_X4(r0, r1, r2, r3, addr)                                          \
    asm volatile("ldmatrix.sync.aligned.m8n8.x4.shared.b16 {%0,%1,%2,%3}, [%4];" \
                 : "=r"(r0), "=r"(r1), "=r"(r2), "=r"(r3) : "r"(addr))

#define MMA16816(d, a, b)                                                      \
    asm volatile("mma.sync.aligned.m16n8k16.row.col.f32.f16.f16.f32 "          \
                 "{%0,%1,%2,%3}, {%4,%5,%6,%7}, {%8,%9}, {%0,%1,%2,%3};"       \
                 : "+f"((d)[0]), "+f"((d)[1]), "+f"((d)[2]), "+f"((d)[3])      \
                 : "r"((a)[0]), "r"((a)[1]), "r"((a)[2]), "r"((a)[3]),         \
                   "r"((b)[0]), "r"((b)[1]))

#define CP_ASYNC16(dst, src)                                                   \
    asm volatile("cp.async.cg.shared.global [%0], [%1], 16;"                   \
                 :: "r"(dst), "l"(src))
#define CP_COMMIT() asm volatile("cp.async.commit_group;" ::: "memory")
#define CP_WAIT(n)  asm volatile("cp.async.wait_group %0;" :: "n"(n) : "memory")

__device__ __forceinline__ uint32_t pack_h2(__half a, __half b) {
    __half2 h = __halves2half2(a, b);
    return *(uint32_t*)&h;
}

// One pipeline stage: A[128][40] then B[128][40] halves (80 B row stride).
#define TSTAGE 20480u
#define MAIN_SMEM (4 * 20480)     // proj: 4-stage
#define SC_SMEM  (3 * 20480)      // scores: 3-stage (only 2 iters)

// Core loop: CTA 128x128, 8 warps (2Mx4N), K-step 32,
// STAGES-deep cp.async pipeline. nIters >= 2 in all uses.
template <int STAGES>
__device__ __forceinline__ void mma_loop_128x128(
    char* smem, const __half* __restrict__ Abase,
    const __half* __restrict__ Bbase,
    int lda, int ldb, int nIters, float acc[4][4][4])
{
    const int tid  = threadIdx.x;
    const int lane = tid & 31;
    const int warp = tid >> 5;
    const int wm = (warp >> 2) * 64;
    const int wn = (warp & 3) * 32;

    const int grow = tid >> 2;
    const int gcol = (tid & 3) * 8;
    const __half* Ap = Abase + (size_t)grow * lda + gcol;
    const __half* Bp = Bbase + (size_t)grow * ldb + gcol;

    const uint32_t s0 = smem_u32(smem);
    const uint32_t aStOff = (uint32_t)(grow * 80 + gcol * 2);
    const uint32_t bStOff = 10240u + (uint32_t)(grow * 80 + gcol * 2);

    const int mrow  = lane & 15;
    const int kA    = (lane & 16) ? 16 : 0;
    const int nrow  = (lane & 7) + ((lane & 16) ? 8 : 0);
    const int kB    = (lane & 8) ? 16 : 0;
    const uint32_t aLdm = s0 + (uint32_t)((wm + mrow) * 80 + kA);
    const uint32_t bLdm = s0 + 10240u + (uint32_t)((wn + nrow) * 80 + kB);

#define ISSUE_TILE(g)                                                          \
    do {                                                                       \
        const uint32_t st = s0 + (uint32_t)((g) % STAGES) * TSTAGE;            \
        const __half* An = Ap + (g) * 32;                                      \
        const __half* Bn = Bp + (g) * 32;                                      \
        CP_ASYNC16(st + aStOff, An);                                           \
        CP_ASYNC16(st + aStOff + 64u * 80u, An + (size_t)64 * lda);            \
        CP_ASYNC16(st + bStOff, Bn);                                           \
        CP_ASYNC16(st + bStOff + 64u * 80u, Bn + (size_t)64 * ldb);            \
        CP_COMMIT();                                                           \
    } while (0)

#pragma unroll
    for (int p = 0; p < STAGES - 1; ++p) ISSUE_TILE(p);

    for (int it = 0; it < nIters; ++it) {
        const int rem = nIters - 1 - it;   // tiles after this one
        if (STAGES >= 4 && rem >= 2)      { CP_WAIT(2); }
        else if (rem >= 1)                { CP_WAIT(1); }
        else                              { CP_WAIT(0); }
        __syncthreads();
        if (it + STAGES - 1 < nIters) ISSUE_TILE(it + STAGES - 1);

        const uint32_t cur = (uint32_t)(it % STAGES) * TSTAGE;
#pragma unroll
        for (int ks = 0; ks < 2; ++ks) {
            uint32_t a[4][4], b[4][2];
#pragma unroll
            for (int mi = 0; mi < 4; ++mi)
                LDSM_X4(a[mi][0], a[mi][1], a[mi][2], a[mi][3],
                        aLdm + cur + (uint32_t)(mi * 16 * 80 + ks * 32));
            LDSM_X4(b[0][0], b[0][1], b[1][0], b[1][1],
                    bLdm + cur + (uint32_t)(ks * 32));
            LDSM_X4(b[2][0], b[2][1], b[3][0], b[3][1],
                    bLdm + cur + (uint32_t)(16 * 80 + ks * 32));
#pragma unroll
            for (int mi = 0; mi < 4; ++mi)
#pragma unroll
                for (int ni = 0; ni < 4; ++ni)
                    MMA16816(acc[mi][ni], a[mi], b[ni]);
        }
    }
#undef ISSUE_TILE
}

// ---------------------------------------------------------------------------
// Merged Q/K/V projection: grid (8, 64, 3). z=0:Q, z=1:K, z=2:V.
// ---------------------------------------------------------------------------
struct QKVArgs {
    const __half* A[3];
    const __half* W[3];
    const float*  bias[3];
    __half*       C[3];
};

__global__ __launch_bounds__(256) void proj_qkv(QKVArgs args)
{
    extern __shared__ char smem[];
    const int zk = blockIdx.z;       // 0=Q, 1=K, 2=V
    const int mbase = blockIdx.y * 128;
    const int nbase = blockIdx.x * 128;

    const __half* Ag = args.A[zk];
    const __half* Bg = args.W[zk];
    const float* bias = args.bias[zk];
    __half* Cs = args.C[zk];

    float acc[4][4][4];
#pragma unroll
    for (int i = 0; i < 4; i++)
#pragma unroll
        for (int j = 0; j < 4; j++)
#pragma unroll
            for (int r = 0; r < 4; r++) acc[i][j][r] = 0.0f;

    mma_loop_128x128<4>(smem, Ag + (size_t)mbase * GK, Bg + (size_t)nbase * GK,
                        GK, GK, GK / 32, acc);

    const int lane = threadIdx.x & 31;
    const int warp = threadIdx.x >> 5;
    const int wm = (warp >> 2) * 64;
    const int wn = (warp & 3) * 32;
    const int g = lane >> 2, tg = lane & 3;

#pragma unroll
    for (int mi = 0; mi < 4; ++mi) {
#pragma unroll
        for (int ni = 0; ni < 4; ++ni) {
#pragma unroll
            for (int half = 0; half < 2; ++half) {
                const int m = mbase + wm + mi * 16 + g + half * 8;
                const int n0 = nbase + wn + ni * 8 + tg * 2;
                float v0 = acc[mi][ni][half * 2 + 0] + bias[n0];
                float v1 = acc[mi][ni][half * 2 + 1] + bias[n0 + 1];
                const int z = ((m >> 11) << 4) + (n0 >> 6);
                const int s = m & (SEQ - 1);
                const int d = n0 & 63;
                if (zk == 0) { v0 *= 0.125f; v1 *= 0.125f; }
                const __half h0 = __float2half_rn(v0);
                const __half h1 = __float2half_rn(v1);
                if (zk == 0 || zk == 1) {   // Q/K heads: single fp16 [z,s,64]
                    __half* p = Cs + ((size_t)z * SEQ + s) * SK;
                    *(uint32_t*)(p + d) = pack_h2(h0, h1);
                } else {                    // V^T fp16 [z][d][s]
                    const size_t b0 = ((size_t)z * DHEAD + d) * VK + s;
                    Cs[b0]      = h0;
                    Cs[b0 + VK] = h1;       // d+1 row
                }
            }
        }
    }
}

// ---------------------------------------------------------------------------
// Output projection: D[8192,1024] fp32 = ohs[8192,1024] x wos[1024,1024]^T + bias
// ---------------------------------------------------------------------------
__global__ __launch_bounds__(256) void proj_out(
    const __half* __restrict__ Ag, const __half* __restrict__ Bg,
    const float* __restrict__ bias, float* __restrict__ Cf)
{
    extern __shared__ char smem[];
    const int mbase = blockIdx.y * 128;
    const int nbase = blockIdx.x * 128;

    float acc[4][4][4];
#pragma unroll
    for (int i = 0; i < 4; i++)
#pragma unroll
        for (int j = 0; j < 4; j++)
#pragma unroll
            for (int r = 0; r < 4; r++) acc[i][j][r] = 0.0f;

    mma_loop_128x128<4>(smem, Ag + (size_t)mbase * GK, Bg + (size_t)nbase * GK,
                        GK, GK, GK / 32, acc);

    const int lane = threadIdx.x & 31;
    const int warp = threadIdx.x >> 5;
    const int wm = (warp >> 2) * 64;
    const int wn = (warp & 3) * 32;
    const int g = lane >> 2, tg = lane & 3;

#pragma unroll
    for (int mi = 0; mi < 4; ++mi) {
#pragma unroll
        for (int ni = 0; ni < 4; ++ni) {
#pragma unroll
            for (int half = 0; half < 2; ++half) {
                const int m = mbase + wm + mi * 16 + g + half * 8;
                const int n0 = nbase + wn + ni * 8 + tg * 2;
                float v0 = acc[mi][ni][half * 2 + 0] + bias[n0];
                float v1 = acc[mi][ni][half * 2 + 1] + bias[n0 + 1];
                *(float2*)&Cf[(size_t)m * DMODEL + n0] = make_float2(v0, v1);
            }
        }
    }
}

// ---------------------------------------------------------------------------
// Scores GEMM per head-slice z (K=64, single fp16): writes e = exp(score)
// fp16 to g_eh and per-row partial sums to psum[row][blockIdx.x].
// ---------------------------------------------------------------------------
__global__ __launch_bounds__(256) void scores_mma(
    const __half* __restrict__ qsp, const __half* __restrict__ ksp,
    __half* __restrict__ eh, float* __restrict__ psum)
{
    extern __shared__ char smem[];
    __shared__ float rowpart[4][128];
    const int z     = blockIdx.z;
    const int qbase = blockIdx.y * 128;
    const int kbase = blockIdx.x * 128;

    float acc[4][4][4];
#pragma unroll
    for (int i = 0; i < 4; i++)
#pragma unroll
        for (int j = 0; j < 4; j++)
#pragma unroll
            for (int r = 0; r < 4; r++) acc[i][j][r] = 0.0f;

    const __half* Abase = qsp + ((size_t)z * SEQ + qbase) * SK;
    const __half* Bbase = ksp + ((size_t)z * SEQ + kbase) * SK;
    mma_loop_128x128<3>(smem, Abase, Bbase, SK, SK, SK / 32, acc);

    const int lane = threadIdx.x & 31;
    const int warp = threadIdx.x >> 5;
    const int wm = (warp >> 2) * 64;
    const int wn = (warp & 3) * 32;
    const int g = lane >> 2, tg = lane & 3;

    __half* out = eh + ((size_t)z * SEQ + qbase) * SEQ + kbase;
#pragma unroll
    for (int mi = 0; mi < 4; ++mi) {
#pragma unroll
        for (int half = 0; half < 2; ++half) {
            const int r = wm + mi * 16 + g + half * 8;
            float s8 = 0.0f;
#pragma unroll
            for (int ni = 0; ni < 4; ++ni) {
                const int c = wn + ni * 8 + tg * 2;
                const __half h0 = __float2half_rn(__expf(acc[mi][ni][half * 2 + 0]));
                const __half h1 = __float2half_rn(__expf(acc[mi][ni][half * 2 + 1]));
                *(uint32_t*)&out[(size_t)r * SEQ + c] = pack_h2(h0, h1);
                s8 += __half2float(h0) + __half2float(h1);
            }
            s8 += __shfl_xor_sync(0xffffffffu, s8, 1);
            s8 += __shfl_xor_sync(0xffffffffu, s8, 2);
            if (tg == 0) rowpart[warp & 3][r] = s8;
        }
    }
    __syncthreads();
    if (threadIdx.x < 128) {
        const float s = (rowpart[0][threadIdx.x] + rowpart[1][threadIdx.x])
                      + (rowpart[2][threadIdx.x] + rowpart[3][threadIdx.x]);
        psum[((size_t)z * SEQ + qbase + threadIdx.x) * 16 + blockIdx.x] = s;
    }
}

// ---------------------------------------------------------------------------
// AV GEMM (single fp16 p and V): per z: O[q,d] = sum_k p[q,k] V[k,d].
// CTA 128x64, K_eff = 2048. Stage = A(10240) + B(5120) = 15360 B.
// ---------------------------------------------------------------------------
#define AV_STAGE 15360u
#define AV_SMEM  (2 * 15360)

__global__ __launch_bounds__(256) void av_mma(
    const __half* __restrict__ eh, float* __restrict__ attn,
    const float* __restrict__ psum,
    const __half* __restrict__ vsp, __half* __restrict__ ohs)
{
    extern __shared__ char smem[];
    const int z = blockIdx.y;
    const int mbase = blockIdx.x * 128;
    const int b = z >> 4, h = z & 15;
    const int tid = threadIdx.x, lane = tid & 31, warp = tid >> 5;
    const int wm = (warp >> 1) * 32, wn = (warp & 1) * 32;

    const __half* E = eh + ((size_t)z * SEQ + mbase) * SEQ;
    float* P = attn + ((size_t)z * SEQ + mbase) * SEQ;
    const __half* Vb = vsp + (size_t)z * DHEAD * VK;
    const float* ps = psum + ((size_t)z * SEQ + mbase) * 16;

    float inv[2];
#pragma unroll
    for (int i = 0; i < 2; ++i) {
        const int row = (tid + i * 256) >> 2;
        const float* pr = ps + (size_t)row * 16;
        float s = 0.0f;
#pragma unroll
        for (int j = 0; j < 16; ++j) s += pr[j];
        inv[i] = 1.0f / s;
    }

    float acc[2][4][4];
#pragma unroll
    for (int i = 0; i < 2; i++)
#pragma unroll
        for (int j = 0; j < 4; j++)
#pragma unroll
            for (int r = 0; r < 4; r++) acc[i][j][r] = 0.0f;

    const uint32_t s0 = smem_u32(smem);
    const int mrow = lane & 15;
    const int kA = (lane & 16) ? 16 : 0;
    const int nr = (lane & 7) + ((lane & 16) ? 8 : 0);
    const int kB = (lane & 8) ? 16 : 0;

#define AV_ISSUE_V(gIt)                                                        \
    do {                                                                       \
        const uint32_t st = s0 + (uint32_t)((gIt) & 1) * AV_STAGE + 10240u;    \
        const int d = tid >> 2, jc = (tid & 3) * 8;                            \
        CP_ASYNC16(st + (uint32_t)(d * 80 + jc * 2),                           \
                   Vb + (size_t)d * VK + (gIt) * 32 + jc);                     \
        CP_COMMIT();                                                           \
    } while (0)

    AV_ISSUE_V(0);

    uint4 pe[2];
#pragma unroll
    for (int i = 0; i < 2; ++i) {
        const int idx = tid + i * 256;
        const int row = idx >> 2, c8 = (idx & 3) * 8;
        pe[i] = *(const uint4*)&E[(size_t)row * SEQ + c8];
    }

    const int nIt = SEQ / 32;   // 64
    for (int it = 0; it < nIt; ++it) {
        const uint32_t stOff = (uint32_t)(it & 1) * AV_STAGE;
#pragma unroll
        for (int i = 0; i < 2; ++i) {
            const int idx = tid + i * 256;
            const int row = idx >> 2, c8 = (idx & 3) * 8;
            const __half2* eh2 = (const __half2*)&pe[i];
            float p[8];
#pragma unroll
            for (int j = 0; j < 4; ++j) {
                float2 f = __half22float2(eh2[j]);
                p[2 * j]     = f.x * inv[i];
                p[2 * j + 1] = f.y * inv[i];
            }
            float* Pw = &P[(size_t)row * SEQ + it * 32 + c8];
            __stcs((float4*)(Pw),     make_float4(p[0], p[1], p[2], p[3]));
            __stcs((float4*)(Pw + 4), make_float4(p[4], p[5], p[6], p[7]));
            uint4 hp;
            __half hh[8];
#pragma unroll
            for (int j = 0; j < 8; ++j) hh[j] = __float2half_rn(p[j]);
            hp.x = pack_h2(hh[0], hh[1]); hp.y = pack_h2(hh[2], hh[3]);
            hp.z = pack_h2(hh[4], hh[5]); hp.w = pack_h2(hh[6], hh[7]);
            *(uint4*)(smem + stOff + (uint32_t)(row * 80 + c8 * 2)) = hp;
        }
        if (it + 1 < nIt) {
#pragma unroll
            for (int i = 0; i < 2; ++i) {
                const int idx = tid + i * 256;
                const int row = idx >> 2, c8 = (idx & 3) * 8;
                pe[i] = *(const uint4*)&E[(size_t)row * SEQ + (it + 1) * 32 + c8];
            }
        }
        CP_WAIT(0);
        __syncthreads();
        if (it + 1 < nIt) AV_ISSUE_V(it + 1);

        const uint32_t aBase = s0 + stOff;
        const uint32_t bBase = s0 + stOff + 10240u;
#pragma unroll
        for (int ks = 0; ks < 2; ++ks) {
            uint32_t a[2][4], bq[4][2];
#pragma unroll
            for (int mi = 0; mi < 2; ++mi)
                LDSM_X4(a[mi][0], a[mi][1], a[mi][2], a[mi][3],
                        aBase + (uint32_t)((wm + mi * 16 + mrow) * 80 + kA + ks * 32));
            LDSM_X4(bq[0][0], bq[0][1], bq[1][0], bq[1][1],
                    bBase + (uint32_t)((wn + nr) * 80 + kB + ks * 32));
            LDSM_X4(bq[2][0], bq[2][1], bq[3][0], bq[3][1],
                    bBase + (uint32_t)((wn + 16 + nr) * 80 + kB + ks * 32));
#pragma unroll
            for (int mi = 0; mi < 2; ++mi)
#pragma unroll
                for (int ni = 0; ni < 4; ++ni)
                    MMA16816(acc[mi][ni], a[mi], bq[ni]);
        }
    }
#undef AV_ISSUE_V

    // epilogue -> g_ohs single fp16 [m, 1024]
    const int g = lane >> 2, tg = lane & 3;
#pragma unroll
    for (int mi = 0; mi < 2; ++mi) {
#pragma unroll
        for (int ni = 0; ni < 4; ++ni) {
#pragma unroll
            for (int half = 0; half < 2; ++half) {
                const int r = wm + mi * 16 + g + half * 8;
                const int c = wn + ni * 8 + tg * 2;
                const __half h0 = __float2half_rn(acc[mi][ni][half * 2 + 0]);
                const __half h1 = __float2half_rn(acc[mi][ni][half * 2 + 1]);
                const size_t row = (size_t)(b * SEQ + mbase + r);
                *(uint32_t*)&ohs[row * GK + h * DHEAD + c] = pack_h2(h0, h1);
            }
        }
    }
}

// ---------------------------------------------------------------------------
// Merged prep_act: grid (total4/256, 3). X[R,1024] fp32 -> Y[R,1024] fp16
// ---------------------------------------------------------------------------
struct PrepActArgs { const float* X[3]; __half* Y[3]; };

__global__ __launch_bounds__(256) void prep_act3(PrepActArgs args)
{
    const float* X = args.X[blockIdx.y];
    __half* Y = args.Y[blockIdx.y];
    int i = blockIdx.x * 256 + threadIdx.x;
    float4 xv = ((const float4*)X)[i];
    __half* p = Y + (size_t)i * 4;
    *(uint32_t*)(p)     = pack_h2(__float2half_rn(xv.x), __float2half_rn(xv.y));
    *(uint32_t*)(p + 2) = pack_h2(__float2half_rn(xv.z), __float2half_rn(xv.w));
}

// ---------------------------------------------------------------------------
// Merged prep_wgt: grid (32, 32, 4). W[1024,1024] -> Ws[N=1024,1024] fp16
// ---------------------------------------------------------------------------
struct PrepWgtArgs { const float* W[4]; __half* Ws[4]; };

__global__ __launch_bounds__(256) void prep_wgt4(PrepWgtArgs args)
{
    const float* W = args.W[blockIdx.z];
    __half* Ws = args.Ws[blockIdx.z];
    __shared__ float t[32][33];
    const int k0 = blockIdx.y * 32, n0 = blockIdx.x * 32;
    const int tx = threadIdx.x, ty = threadIdx.y;   // (32, 8)
#pragma unroll
    for (int r = ty; r < 32; r += 8)
        t[r][tx] = W[(size_t)(k0 + r) * DMODEL + n0 + tx];
    __syncthreads();
#pragma unroll
    for (int r = ty; r < 32; r += 8) {
        const int n = n0 + r;
        const int k = k0 + tx;
        Ws[(size_t)n * GK + k] = __float2half_rn(t[tx][r]);
    }
}

// ---------------------------------------------------------------------------
extern "C" void kernel_launch(void* const* d_in, const int* in_sizes, int n_in,
                              void* d_out, int out_size)
{
    const float* q  = (const float*)d_in[0];
    const float* k  = (const float*)d_in[1];
    const float* v  = (const float*)d_in[2];
    const float* Wq = (const float*)d_in[3];
    const float* bq = (const float*)d_in[4];
    const float* Wk = (const float*)d_in[5];
    const float* bk = (const float*)d_in[6];
    const float* Wv = (const float*)d_in[7];
    const float* bv = (const float*)d_in[8];
    const float* Wo = (const float*)d_in[9];
    const float* bo = (const float*)d_in[10];

    float* out  = (float*)d_out;
    float* attn = out + OUT_ELEMS;

    __half *qs, *ks, *vs, *ohs, *wqs, *wks, *wvs, *wos, *qsp, *ksp, *vsp, *ehp;
    float* psum;
    cudaGetSymbolAddress((void**)&qs,  g_qs);
    cudaGetSymbolAddress((void**)&ks,  g_ks);
    cudaGetSymbolAddress((void**)&vs,  g_vs);
    cudaGetSymbolAddress((void**)&ohs, g_ohs);
    cudaGetSymbolAddress((void**)&wqs, g_wqs);
    cudaGetSymbolAddress((void**)&wks, g_wks);
    cudaGetSymbolAddress((void**)&wvs, g_wvs);
    cudaGetSymbolAddress((void**)&wos, g_wos);
    cudaGetSymbolAddress((void**)&qsp, g_qsp);
    cudaGetSymbolAddress((void**)&ksp, g_ksp);
    cudaGetSymbolAddress((void**)&vsp, g_vsp);
    cudaGetSymbolAddress((void**)&ehp, g_eh);
    cudaGetSymbolAddress((void**)&psum, g_psum);

    cudaFuncSetAttribute(proj_qkv,   cudaFuncAttributeMaxDynamicSharedMemorySize, MAIN_SMEM);
    cudaFuncSetAttribute(proj_out,   cudaFuncAttributeMaxDynamicSharedMemorySize, MAIN_SMEM);
    cudaFuncSetAttribute(scores_mma, cudaFuncAttributeMaxDynamicSharedMemorySize, SC_SMEM);
    cudaFuncSetAttribute(av_mma,     cudaFuncAttributeMaxDynamicSharedMemorySize, AV_SMEM);

    const int act4 = MROWS * DMODEL / 4;   // 2097152 -> 8192 blocks

    // 0) fp16 conversions (merged launches)
    PrepWgtArgs wargs;
    wargs.W[0] = Wq; wargs.W[1] = Wk; wargs.W[2] = Wv; wargs.W[3] = Wo;
    wargs.Ws[0] = wqs; wargs.Ws[1] = wks; wargs.Ws[2] = wvs; wargs.Ws[3] = wos;
    prep_wgt4<<<dim3(32, 32, 4), dim3(32, 8)>>>(wargs);

    PrepActArgs aargs;
    aargs.X[0] = q; aargs.X[1] = k; aargs.X[2] = v;
    aargs.Y[0] = qs; aargs.Y[1] = ks; aargs.Y[2] = vs;
    prep_act3<<<dim3(act4 / 256, 3), 256>>>(aargs);

    // 1) Q/K/V projections merged (HMMA): grid (8, 64, 3)
    QKVArgs pargs;
    pargs.A[0] = qs;  pargs.A[1] = ks;  pargs.A[2] = vs;
    pargs.W[0] = wqs; pargs.W[1] = wks; pargs.W[2] = wvs;
    pargs.bias[0] = bq; pargs.bias[1] = bk; pargs.bias[2] = bv;
    pargs.C[0] = qsp; pargs.C[1] = ksp; pargs.C[2] = vsp;
    proj_qkv<<<dim3(DMODEL / 128, MROWS / 128, 3), 256, MAIN_SMEM>>>(pargs);

    // 2) Scores (K=64) -> e = exp(score) fp16 into g_eh + row partial sums
    dim3 gs(SEQ / 128, SEQ / 128, NZ);  // (16, 16, 64)
    scores_mma<<<gs, 256, SC_SMEM>>>(qsp, ksp, ehp, psum);

    // 3) AV (K=2048 single): normalize, write attn fp32, O -> g_ohs fp16
    dim3 ga(SEQ / 128, NZ);  // (16, 64)
    av_mma<<<ga, 256, AV_SMEM>>>(ehp, attn, psum, vsp, ohs);

    // 4) Output projection -> d_out
    proj_out<<<dim3(DMODEL / 128, MROWS / 128), 256, MAIN_SMEM>>>(ohs, wos, bo, out);
}